// round 14
// baseline (speedup 1.0000x reference)
#include <cuda_runtime.h>
#include <cuda_bf16.h>
#include <math.h>
#include <stdint.h>

// Problem constants
#define T_STEPS 1024
#define B_SZ    64
#define IN_SZ   512
#define HID_SZ  512
#define NCOL    2048               // 4 gates * HID
#define M_ROWS  (T_STEPS * B_SZ)   // 65536
#define N_CTAS  128

// ---------------- device scratch (static; no runtime allocation) ------------
__device__ __nv_bfloat16 g_XH[(size_t)M_ROWS * IN_SZ];   // X hi split
__device__ __nv_bfloat16 g_XL[(size_t)M_ROWS * IN_SZ];   // X lo split
__device__ __nv_bfloat16 g_WXH[NCOL * IN_SZ];            // Wx hi [col][k]
__device__ __nv_bfloat16 g_WXL[NCOL * IN_SZ];            // Wx lo [col][k]
__device__ __nv_bfloat16 g_WHH[NCOL * HID_SZ];           // Wh hi [col][k]
__device__ __nv_bfloat16 g_WHL[NCOL * HID_SZ];           // Wh lo [col][k]
__device__ __nv_bfloat16 g_HBH[2][B_SZ * HID_SZ];        // H hi [b][k], dbl buf
__device__ __nv_bfloat16 g_HBL[2][B_SZ * HID_SZ];        // H lo [b][k], dbl buf
__device__ unsigned int g_flags[N_CTAS * 32];            // 1 flag / 128B line

// ---------------- helpers -----------------------------------------------------
__device__ __forceinline__ void split_bf16(float x, __nv_bfloat16& hi,
                                           __nv_bfloat16& lo) {
    hi = __float2bfloat16_rn(x);
    lo = __float2bfloat16_rn(x - __bfloat162float(hi));
}
__device__ __forceinline__ uint32_t smem_u32(const void* p) {
    uint32_t a;
    asm("{ .reg .u64 t; cvta.to.shared.u64 t, %1; cvt.u32.u64 %0, t; }"
        : "=r"(a) : "l"(p));
    return a;
}
__device__ __forceinline__ void cpasync16(uint32_t smem_dst, const void* gsrc) {
    asm volatile("cp.async.cg.shared.global [%0], [%1], 16;"
                 :: "r"(smem_dst), "l"(gsrc));
}
__device__ __forceinline__ void cpasync_commit() {
    asm volatile("cp.async.commit_group;");
}
__device__ __forceinline__ void ldsm4(uint32_t* r, uint32_t addr) {
    asm volatile("ldmatrix.sync.aligned.m8n8.x4.shared.b16 {%0,%1,%2,%3}, [%4];"
                 : "=r"(r[0]), "=r"(r[1]), "=r"(r[2]), "=r"(r[3]) : "r"(addr));
}
__device__ __forceinline__ void mma16816(float* c, const uint32_t* a,
                                         const uint32_t* b) {
    asm volatile(
        "mma.sync.aligned.m16n8k16.row.col.f32.bf16.bf16.f32 "
        "{%0,%1,%2,%3}, {%4,%5,%6,%7}, {%8,%9}, {%0,%1,%2,%3};"
        : "+f"(c[0]), "+f"(c[1]), "+f"(c[2]), "+f"(c[3])
        : "r"(a[0]), "r"(a[1]), "r"(a[2]), "r"(a[3]), "r"(b[0]), "r"(b[1]));
}
__device__ __forceinline__ float fsig(float x) {
    return 1.0f / (1.0f + __expf(-x));
}
__device__ __forceinline__ float ftanh(float x) {
    return 1.0f - 2.0f / (__expf(2.0f * x) + 1.0f);
}
__device__ __forceinline__ unsigned int ld_rlx(const unsigned int* p) {
    unsigned int v;
    asm volatile("ld.relaxed.gpu.global.u32 %0, [%1];" : "=r"(v) : "l"(p) : "memory");
    return v;
}
__device__ __forceinline__ void st_rel(unsigned int* p, unsigned int v) {
    asm volatile("st.release.gpu.global.u32 [%0], %1;" :: "l"(p), "r"(v) : "memory");
}
__device__ __forceinline__ void fence_acq() {
    asm volatile("fence.acq_rel.gpu;" ::: "memory");
}
// L1-bypassing bf16 store (publish path: consumers read from L2 via cp.async)
__device__ __forceinline__ void st_cg_bf16(__nv_bfloat16* p, __nv_bfloat16 v) {
    unsigned short u = *reinterpret_cast<unsigned short*>(&v);
    asm volatile("st.global.cg.u16 [%0], %1;" :: "l"(p), "h"(u) : "memory");
}

// ---------------- kernel 1: threshold-mask + bf16 hi/lo weight splits --------
__global__ void mask_weights(const float* __restrict__ Wx,
                             const float* __restrict__ Wh,
                             const float* __restrict__ thr) {
    int idx = blockIdx.x * blockDim.x + threadIdx.x;   // over 4*512*512
    if (idx >= 4 * HID_SZ * IN_SZ) return;
    int g = idx / (HID_SZ * IN_SZ);
    int rem = idx % (HID_SZ * IN_SZ);
    int n = rem / IN_SZ;
    int i = rem % IN_SZ;
    size_t o = (size_t)(g * HID_SZ + n) * IN_SZ + i;

    float wx = Wx[idx];
    float vx = (fabsf(wx) >= thr[n * 8 + g]) ? wx : 0.0f;
    split_bf16(vx, g_WXH[o], g_WXL[o]);

    float wh = Wh[idx];
    float vh = (fabsf(wh) >= thr[n * 8 + 4 + g]) ? wh : 0.0f;
    split_bf16(vh, g_WHH[o], g_WHL[o]);
}

// ---------------- kernel 2: split X into bf16 hi/lo ---------------------------
__global__ void split_x(const float* __restrict__ X) {
    size_t i = ((size_t)blockIdx.x * blockDim.x + threadIdx.x) * 4;
    if (i >= (size_t)M_ROWS * IN_SZ) return;
    float4 x = *(const float4*)&X[i];
    __nv_bfloat16 h[4], l[4];
    split_bf16(x.x, h[0], l[0]);
    split_bf16(x.y, h[1], l[1]);
    split_bf16(x.z, h[2], l[2]);
    split_bf16(x.w, h[3], l[3]);
    *(__nv_bfloat162*)&g_XH[i]     = __nv_bfloat162(h[0], h[1]);
    *(__nv_bfloat162*)&g_XH[i + 2] = __nv_bfloat162(h[2], h[3]);
    *(__nv_bfloat162*)&g_XL[i]     = __nv_bfloat162(l[0], l[1]);
    *(__nv_bfloat162*)&g_XL[i + 2] = __nv_bfloat162(l[2], l[3]);
}

// ---------------- kernel: reset barrier flags (runs BEFORE lstm) --------------
__global__ void reset_flags() {
    if (threadIdx.x < N_CTAS) g_flags[threadIdx.x * 32] = 0u;
}

// ---------------- kernel 3: fused persistent LSTM (recurrent + input GEMM) ----
// 128 CTAs = 64 col-groups x 2 batch-halves; CTA = 32 batches x 32 gate-cols.
// 8 warps = 2k x 2m x 2n. Per step, each (wk,wm) 64-thread group polls ONLY
// the 32 producer flags of its k-half (cg 0-31 for wk=0, 32-63 for wk=1),
// then stages its H block immediately — overlapping barrier skew with staging.
// Wx resident; XG(t+1) computed in the publish window. X aliases H region.
#define L_WROW  520
#define L_WSPL  33280                   // bytes per W split (32 x 520 x 2B)
#define L_WMAT  66560                   // per matrix (hi+lo)
#define L_WXB   66560                   // Wx base
#define L_HXB   133120                  // H/X shared region base
#define L_HSPL  16896                   // per H split per k-chunk (32 x 264 x 2B)
#define L_HCH   33792                   // per k-chunk (hi+lo)
#define L_XSPL  33280                   // per X split (32 x 520 x 2B)
#define L_GSB   200704                  // Gs base (133120 + 67584)
#define L_SMEM  (L_GSB + 2 * 32 * 36 * 4)   // 209920

__device__ __forceinline__ void stage_x(uint32_t sb, int tstep, int bh, int tid) {
#pragma unroll
    for (int j = 0; j < 16; j++) {
        int lin = j * 256 + tid;        // 0..4095
        int split = lin >> 11;
        int row = (lin >> 6) & 31;      // batch row
        int seg = lin & 63;             // 16B segment (512 k total)
        const __nv_bfloat16* src =
            (split ? g_XL : g_XH) +
            ((size_t)(tstep * B_SZ + bh * 32 + row)) * IN_SZ + seg * 8;
        cpasync16(sb + L_HXB + (uint32_t)split * L_XSPL + row * 1040 + seg * 16,
                  src);
    }
    cpasync_commit();
}

__global__ void __launch_bounds__(256, 1)
lstm_fused(const float* __restrict__ h0, const float* __restrict__ c0,
           const float* __restrict__ bias, float* __restrict__ out) {
    extern __shared__ char sm[];
    const uint32_t sb = smem_u32(sm);
    float* Gs0 = (float*)(sm + L_GSB);               // [32][36] partial k0
    float* Gs1 = Gs0 + 32 * 36;                      // [32][36] partial k1

    const int tid = threadIdx.x;
    const int wid = tid >> 5;
    const int lane = tid & 31;
    const int wk = wid & 1;         // k-half
    const int wm = (wid >> 1) & 1;  // m-tile (16 batches)
    const int wn = wid >> 2;        // n-tile (16 cols)
    const int grp = wid & 3;        // staging group (wk, wm)
    const int gl = wn * 32 + lane;  // lane within 64-thread group

    const int cta = blockIdx.x;
    const int cg  = cta >> 1;             // col group 0..63
    const int bh  = cta & 1;              // batch half
    const int hu0 = cg * 8;

    const int a_radd = ((lane >> 3) & 1) * 8 + (lane & 7);
    const int a_kadd = ((lane >> 4) & 1) * 8;
    const int b_nadd = ((lane >> 4) & 1) * 8 + (lane & 7);
    const int b_kadd = ((lane >> 3) & 1) * 8;

    // flag this group polls (producers of its k-half, same batch half)
    const unsigned int* my_flag =
        &g_flags[(((wk * 32 + (gl & 31)) * 2) + bh) * 32];

    // Load resident W slices: Wh and Wx, hi+lo (32 rows x 512 k each)
#pragma unroll
    for (int j = 0; j < 32; j++) {
        int lin = j * 256 + tid;        // 0..8191
        int mat = lin >> 12;            // 0: Wh, 1: Wx
        int within = lin & 4095;
        int split = within >> 11;
        int row = (within >> 6) & 31;
        int seg = within & 63;
        size_t gcol = (size_t)((row >> 3) * HID_SZ + hu0 + (row & 7));
        const __nv_bfloat16* src;
        if (mat == 0) src = (split ? g_WHL : g_WHH) + gcol * HID_SZ + seg * 8;
        else          src = (split ? g_WXL : g_WXH) + gcol * IN_SZ + seg * 8;
        cpasync16(sb + (uint32_t)mat * L_WMAT + (uint32_t)split * L_WSPL +
                  row * 1040 + seg * 16, src);
    }
    cpasync_commit();

    // pointwise slot: (local batch pb, unit pj)
    const int pb = tid >> 3;
    const int pj = tid & 7;
    const int bg = bh * 32 + pb;

    float creg = c0[bg * HID_SZ + hu0 + pj];
    const float bi_r = bias[0 * HID_SZ + hu0 + pj];
    const float bf_r = bias[1 * HID_SZ + hu0 + pj];
    const float bo_r = bias[2 * HID_SZ + hu0 + pj];
    const float bc_r = bias[3 * HID_SZ + hu0 + pj];

    // init H buffer 0 and publish flag=1 (loop t=0 polls >= 1)
    {
        float h = h0[bg * HID_SZ + hu0 + pj];
        __nv_bfloat16 hi, lo;
        split_bf16(h, hi, lo);
        st_cg_bf16(&g_HBH[0][bg * HID_SZ + hu0 + pj], hi);
        st_cg_bf16(&g_HBL[0][bg * HID_SZ + hu0 + pj], lo);
    }
    asm volatile("cp.async.wait_group 0;");   // W slices resident
    __syncthreads();
    if (tid == 0) { __threadfence(); st_rel(&g_flags[cta * 32], 1u); }

    // stage X[0] and compute XG(0) partial into accx
    float accx[2][4];
#pragma unroll
    for (int n = 0; n < 2; n++)
#pragma unroll
        for (int c = 0; c < 4; c++) accx[n][c] = 0.0f;

    stage_x(sb, 0, bh, tid);
    asm volatile("cp.async.wait_group 0;");
    __syncthreads();
#pragma unroll
    for (int s = 0; s < 16; s++) {
        uint32_t xh[4], xl[4], wh[4], wl[4];
        uint32_t ra = sb + L_HXB + (uint32_t)(wm * 16 + a_radd) * 1040 +
                      (wk * 256 + s * 16 + a_kadd) * 2;
        ldsm4(xh, ra);
        ldsm4(xl, ra + L_XSPL);
        uint32_t rb = sb + L_WXB + (uint32_t)(wn * 16 + b_nadd) * 1040 +
                      (wk * 256 + s * 16 + b_kadd) * 2;
        ldsm4(wh, rb);
        ldsm4(wl, rb + L_WSPL);
#pragma unroll
        for (int hf = 0; hf < 2; hf++) {
            mma16816(accx[hf], xh, &wh[2 * hf]);
            mma16816(accx[hf], xh, &wl[2 * hf]);
            mma16816(accx[hf], xl, &wh[2 * hf]);
        }
    }
    __syncthreads();   // X buffer free before first H staging

    for (int t = 0; t < T_STEPS; t++) {
        const int cur = t & 1;
        const bool has_next = (t + 1 < T_STEPS);

        // ---- per-group producer wait: only the 32 flags this k-half needs ----
        {
            const unsigned int need = (unsigned)(t + 1);
            if (gl < 32) { while (ld_rlx(my_flag) < need) { } }
            asm volatile("bar.sync %0, 64;" :: "r"(grp + 1) : "memory");
            fence_acq();
        }

        // group (wk,wm) stages its H block in TWO commit halves (k-split)
#pragma unroll
        for (int half = 0; half < 2; half++) {
#pragma unroll
            for (int j = 0; j < 8; j++) {
                int lin = j * 64 + gl;          // 0..511
                int split = lin >> 8;           // hi/lo
                int w = lin & 255;
                int r16 = w >> 4;               // 0..15
                int seg = half * 16 + (w & 15); // 16B seg, k-half selected
                int row = wm * 16 + r16;
                int b = bh * 32 + row;
                const __nv_bfloat16* src =
                    (split ? g_HBL[cur] : g_HBH[cur]) +
                    (size_t)b * HID_SZ + wk * 256 + seg * 8;
                cpasync16(sb + L_HXB + (uint32_t)wk * L_HCH +
                          (uint32_t)split * L_HSPL + row * 528 + seg * 16,
                          src);
            }
            cpasync_commit();
        }

        // recurrent mma, accumulators start from XG partial of this step
        float acc[2][4];
#pragma unroll
        for (int n = 0; n < 2; n++)
#pragma unroll
            for (int c = 0; c < 4; c++) acc[n][c] = accx[n][c];

        const uint32_t hb = sb + L_HXB + (uint32_t)wk * L_HCH;

        asm volatile("cp.async.wait_group 1;");
        asm volatile("bar.sync %0, 64;" :: "r"(grp + 1) : "memory");
#pragma unroll
        for (int s = 0; s < 8; s++) {
            uint32_t ah[4], al[4], bhq[4], blq[4];
            uint32_t ra = hb + (uint32_t)(wm * 16 + a_radd) * 528 +
                          (s * 16 + a_kadd) * 2;
            ldsm4(ah, ra);
            ldsm4(al, ra + L_HSPL);
            uint32_t rb = sb + (uint32_t)(wn * 16 + b_nadd) * 1040 +
                          (wk * 256 + s * 16 + b_kadd) * 2;
            ldsm4(bhq, rb);
            ldsm4(blq, rb + L_WSPL);
#pragma unroll
            for (int hf = 0; hf < 2; hf++) {
                mma16816(acc[hf], ah, &bhq[2 * hf]);
                mma16816(acc[hf], ah, &blq[2 * hf]);
                mma16816(acc[hf], al, &bhq[2 * hf]);
            }
        }
        asm volatile("cp.async.wait_group 0;");
        asm volatile("bar.sync %0, 64;" :: "r"(grp + 1) : "memory");
#pragma unroll
        for (int s = 8; s < 16; s++) {
            uint32_t ah[4], al[4], bhq[4], blq[4];
            uint32_t ra = hb + (uint32_t)(wm * 16 + a_radd) * 528 +
                          (s * 16 + a_kadd) * 2;
            ldsm4(ah, ra);
            ldsm4(al, ra + L_HSPL);
            uint32_t rb = sb + (uint32_t)(wn * 16 + b_nadd) * 1040 +
                          (wk * 256 + s * 16 + b_kadd) * 2;
            ldsm4(bhq, rb);
            ldsm4(blq, rb + L_WSPL);
#pragma unroll
            for (int hf = 0; hf < 2; hf++) {
                mma16816(acc[hf], ah, &bhq[2 * hf]);
                mma16816(acc[hf], ah, &blq[2 * hf]);
                mma16816(acc[hf], al, &bhq[2 * hf]);
            }
        }

        // write partial G frags to this k-half's buffer
        {
            float* Gd = wk ? Gs1 : Gs0;
            const int g = lane >> 2, t2 = (lane & 3) * 2;
#pragma unroll
            for (int nt = 0; nt < 2; nt++) {
                int row = wm * 16 + g;
                int col = wn * 16 + nt * 8 + t2;
                *(float2*)&Gd[row * 36 + col] = make_float2(acc[nt][0], acc[nt][1]);
                *(float2*)&Gd[(row + 8) * 36 + col] = make_float2(acc[nt][2], acc[nt][3]);
            }
        }
        __syncthreads();    // Gs ready; all H reads done -> X buf reusable

        // stage X[t+1] into the (now free) H/X shared buffer
        if (has_next) stage_x(sb, t + 1, bh, tid);

        // pointwise LSTM cell
        const unsigned int sense = (unsigned)(t + 2);
        float h;
        {
            float gi = Gs0[pb * 36 + 0  + pj] + Gs1[pb * 36 + 0  + pj] + bi_r;
            float gf = Gs0[pb * 36 + 8  + pj] + Gs1[pb * 36 + 8  + pj] + bf_r;
            float go = Gs0[pb * 36 + 16 + pj] + Gs1[pb * 36 + 16 + pj] + bo_r;
            float gc = Gs0[pb * 36 + 24 + pj] + Gs1[pb * 36 + 24 + pj] + bc_r;
            float I = fsig(gi);
            float F = fsig(gf);
            float O = fsig(go);
            float Ct = ftanh(gc);
            creg = F * creg + I * Ct;
            h = O * ftanh(creg);
        }

        if (has_next) {
            // publish H splits straight to L2, arrive on own flag
            {
                __nv_bfloat16 hi, lo;
                split_bf16(h, hi, lo);
                st_cg_bf16(&g_HBH[cur ^ 1][bg * HID_SZ + hu0 + pj], hi);
                st_cg_bf16(&g_HBL[cur ^ 1][bg * HID_SZ + hu0 + pj], lo);
            }
            __syncthreads();             // all H stores issued
            if (tid == 0) {
                __threadfence();
                st_rel(&g_flags[cta * 32], sense);
            }
            out[(size_t)(t * B_SZ + bg) * HID_SZ + hu0 + pj] = h;

            // XG(t+1) in the publish window
#pragma unroll
            for (int n = 0; n < 2; n++)
#pragma unroll
                for (int c = 0; c < 4; c++) accx[n][c] = 0.0f;
            asm volatile("cp.async.wait_group 0;");
            __syncthreads();             // everyone's X parts arrived
#pragma unroll
            for (int s = 0; s < 16; s++) {
                uint32_t xh[4], xl[4], wh[4], wl[4];
                uint32_t ra = sb + L_HXB + (uint32_t)(wm * 16 + a_radd) * 1040 +
                              (wk * 256 + s * 16 + a_kadd) * 2;
                ldsm4(xh, ra);
                ldsm4(xl, ra + L_XSPL);
                uint32_t rb = sb + L_WXB + (uint32_t)(wn * 16 + b_nadd) * 1040 +
                              (wk * 256 + s * 16 + b_kadd) * 2;
                ldsm4(wh, rb);
                ldsm4(wl, rb + L_WSPL);
#pragma unroll
                for (int hf = 0; hf < 2; hf++) {
                    mma16816(accx[hf], xh, &wh[2 * hf]);
                    mma16816(accx[hf], xh, &wl[2 * hf]);
                    mma16816(accx[hf], xl, &wh[2 * hf]);
                }
            }
            __syncthreads();   // X reads done before next iter's H staging
        } else {
            out[(size_t)(t * B_SZ + bg) * HID_SZ + hu0 + pj] = h;
        }
    }
}

// ---------------- launcher ---------------------------------------------------
extern "C" void kernel_launch(void* const* d_in, const int* in_sizes, int n_in,
                              void* d_out, int out_size) {
    const float* X    = (const float*)d_in[0];   // (T,B,IN)
    const float* Wx   = (const float*)d_in[1];   // (4,HID,IN)
    const float* Wh   = (const float*)d_in[2];   // (4,HID,HID)
    const float* bias = (const float*)d_in[3];   // (4,HID)
    const float* thr  = (const float*)d_in[4];   // (HID,8)
    const float* h0   = (const float*)d_in[5];   // (B,HID)
    const float* c0   = (const float*)d_in[6];   // (B,HID)
    float* out = (float*)d_out;                  // (T,B,HID)

    mask_weights<<<(4 * HID_SZ * IN_SZ + 255) / 256, 256>>>(Wx, Wh, thr);
    split_x<<<(M_ROWS * IN_SZ / 4 + 255) / 256, 256>>>(X);

    // reset flags BEFORE lstm (works for replay; also puts lstm at ncu's
    // captured launch position)
    reset_flags<<<1, 128>>>();

    cudaFuncSetAttribute(lstm_fused,
                         cudaFuncAttributeMaxDynamicSharedMemorySize, L_SMEM);
    lstm_fused<<<N_CTAS, 256, L_SMEM>>>(h0, c0, bias, out);
}

// round 15
// speedup vs baseline: 1.3598x; 1.3598x over previous
#include <cuda_runtime.h>
#include <cuda_fp16.h>
#include <math.h>
#include <stdint.h>

// Problem constants
#define T_STEPS 1024
#define B_SZ    64
#define IN_SZ   512
#define HID_SZ  512
#define NCOL    2048               // 4 gates * HID
#define M_ROWS  (T_STEPS * B_SZ)   // 65536
#define N_CTAS  128

// ---------------- device scratch (static; no runtime allocation) ------------
__device__ __half g_XF[(size_t)M_ROWS * IN_SZ];   // X fp16 (single), 64 MB
__device__ __half g_WXH[NCOL * IN_SZ];            // Wx hi fp16 [col][k]
__device__ __half g_WXL[NCOL * IN_SZ];            // Wx lo fp16 [col][k]
__device__ __half g_WHH[NCOL * HID_SZ];           // Wh hi fp16 [col][k]
__device__ __half g_WHL[NCOL * HID_SZ];           // Wh lo fp16 [col][k]
__device__ __half g_HB[2][B_SZ * HID_SZ];         // H fp16 [b][k], dbl buf
__device__ unsigned int g_flags[N_CTAS * 32];     // 1 flag / 128B line

// ---------------- helpers -----------------------------------------------------
__device__ __forceinline__ uint32_t smem_u32(const void* p) {
    uint32_t a;
    asm("{ .reg .u64 t; cvta.to.shared.u64 t, %1; cvt.u32.u64 %0, t; }"
        : "=r"(a) : "l"(p));
    return a;
}
__device__ __forceinline__ void cpasync16(uint32_t smem_dst, const void* gsrc) {
    asm volatile("cp.async.cg.shared.global [%0], [%1], 16;"
                 :: "r"(smem_dst), "l"(gsrc));
}
__device__ __forceinline__ void cpasync_commit() {
    asm volatile("cp.async.commit_group;");
}
__device__ __forceinline__ void ldsm4(uint32_t* r, uint32_t addr) {
    asm volatile("ldmatrix.sync.aligned.m8n8.x4.shared.b16 {%0,%1,%2,%3}, [%4];"
                 : "=r"(r[0]), "=r"(r[1]), "=r"(r[2]), "=r"(r[3]) : "r"(addr));
}
__device__ __forceinline__ void mma16816f(float* c, const uint32_t* a,
                                          const uint32_t* b) {
    asm volatile(
        "mma.sync.aligned.m16n8k16.row.col.f32.f16.f16.f32 "
        "{%0,%1,%2,%3}, {%4,%5,%6,%7}, {%8,%9}, {%0,%1,%2,%3};"
        : "+f"(c[0]), "+f"(c[1]), "+f"(c[2]), "+f"(c[3])
        : "r"(a[0]), "r"(a[1]), "r"(a[2]), "r"(a[3]), "r"(b[0]), "r"(b[1]));
}
__device__ __forceinline__ float fsig(float x) {
    return 1.0f / (1.0f + __expf(-x));
}
__device__ __forceinline__ float ftanh(float x) {
    return 1.0f - 2.0f / (__expf(2.0f * x) + 1.0f);
}
__device__ __forceinline__ unsigned int ld_rlx(const unsigned int* p) {
    unsigned int v;
    asm volatile("ld.relaxed.gpu.global.u32 %0, [%1];" : "=r"(v) : "l"(p) : "memory");
    return v;
}
__device__ __forceinline__ void st_rel(unsigned int* p, unsigned int v) {
    asm volatile("st.release.gpu.global.u32 [%0], %1;" :: "l"(p), "r"(v) : "memory");
}
__device__ __forceinline__ void fence_acq() {
    asm volatile("fence.acq_rel.gpu;" ::: "memory");
}
// L1-bypassing fp16 store (publish path: consumers read from L2 via cp.async)
__device__ __forceinline__ void st_cg_h16(__half* p, __half v) {
    unsigned short u = *reinterpret_cast<unsigned short*>(&v);
    asm volatile("st.global.cg.u16 [%0], %1;" :: "l"(p), "h"(u) : "memory");
}

// ---------------- kernel 1: threshold-mask + fp16 hi/lo weight splits --------
__global__ void mask_weights(const float* __restrict__ Wx,
                             const float* __restrict__ Wh,
                             const float* __restrict__ thr) {
    int idx = blockIdx.x * blockDim.x + threadIdx.x;   // over 4*512*512
    if (idx >= 4 * HID_SZ * IN_SZ) return;
    int g = idx / (HID_SZ * IN_SZ);
    int rem = idx % (HID_SZ * IN_SZ);
    int n = rem / IN_SZ;
    int i = rem % IN_SZ;
    size_t o = (size_t)(g * HID_SZ + n) * IN_SZ + i;

    float wx = Wx[idx];
    float vx = (fabsf(wx) >= thr[n * 8 + g]) ? wx : 0.0f;
    __half xh = __float2half_rn(vx);
    g_WXH[o] = xh;
    g_WXL[o] = __float2half_rn(vx - __half2float(xh));

    float wh = Wh[idx];
    float vh = (fabsf(wh) >= thr[n * 8 + 4 + g]) ? wh : 0.0f;
    __half hh = __float2half_rn(vh);
    g_WHH[o] = hh;
    g_WHL[o] = __float2half_rn(vh - __half2float(hh));
}

// ---------------- kernel 2: convert X to fp16 ---------------------------------
__global__ void split_x(const float* __restrict__ X) {
    size_t i = ((size_t)blockIdx.x * blockDim.x + threadIdx.x) * 4;
    if (i >= (size_t)M_ROWS * IN_SZ) return;
    float4 x = *(const float4*)&X[i];
    __half2* p = (__half2*)&g_XF[i];
    p[0] = __floats2half2_rn(x.x, x.y);
    p[1] = __floats2half2_rn(x.z, x.w);
}

// ---------------- kernel: reset barrier flags (runs BEFORE lstm) --------------
__global__ void reset_flags() {
    if (threadIdx.x < N_CTAS) g_flags[threadIdx.x * 32] = 0u;
}

// ---------------- kernel 3: fused persistent LSTM (fp16 operands) -------------
// 128 CTAs = 64 col-groups x 2 batch-halves; CTA = 32 batches x 32 gate-cols.
// 8 warps = 2k x 2m x 2n. Weights fp16 hi/lo resident; H and X single fp16.
// Per step: stage H (2 commits) + X[t+1] (1 commit) at top -> recurrent mma
// (2 products/s, acc init = accx) -> Gs reduce -> pointwise + publish + flag
// -> XG(t+1) mma in the wait window -> poll own 64-CTA group.
#define WHB   0
#define WXB   66560                 // Wx base (Whh 33280 + Whl 33280)
#define HB    133120                // H: 2 chunks x 16896 (32 rows x 528B)
#define XB    166912                // X: 32 rows x 1040B = 33280
#define GSB   200192                // Gs: 2 x [32][36] f32 = 9216
#define L_SMEM 209408

__device__ __forceinline__ void stage_x(uint32_t sb, int tstep, int bh, int tid) {
#pragma unroll
    for (int j = 0; j < 8; j++) {
        int lin = j * 256 + tid;        // 0..2047
        int row = lin >> 6;             // 0..31
        int seg = lin & 63;             // 16B segment (512 halves)
        const __half* src =
            g_XF + ((size_t)(tstep * B_SZ + bh * 32 + row)) * IN_SZ + seg * 8;
        cpasync16(sb + XB + row * 1040 + seg * 16, src);
    }
    cpasync_commit();
}

__global__ void __launch_bounds__(256, 1)
lstm_fused(const float* __restrict__ h0, const float* __restrict__ c0,
           const float* __restrict__ bias, float* __restrict__ out) {
    extern __shared__ char sm[];
    const uint32_t sb = smem_u32(sm);
    float* Gs0 = (float*)(sm + GSB);                 // [32][36] partial k0
    float* Gs1 = Gs0 + 32 * 36;                      // [32][36] partial k1

    const int tid = threadIdx.x;
    const int wid = tid >> 5;
    const int lane = tid & 31;
    const int wk = wid & 1;         // k-half
    const int wm = (wid >> 1) & 1;  // m-tile (16 batches)
    const int wn = wid >> 2;        // n-tile (16 cols)
    const int grp = wid & 3;        // staging group (wk, wm)
    const int gl = wn * 32 + lane;  // lane within 64-thread group

    const int cta = blockIdx.x;
    const int cg  = cta >> 1;             // col group 0..63
    const int bh  = cta & 1;              // batch half
    const int hu0 = cg * 8;

    const int a_radd = ((lane >> 3) & 1) * 8 + (lane & 7);
    const int a_kadd = ((lane >> 4) & 1) * 8;
    const int b_nadd = ((lane >> 4) & 1) * 8 + (lane & 7);
    const int b_kadd = ((lane >> 3) & 1) * 8;

    // Load resident W splits: WHH, WHL, WXH, WXL (32 rows x 512 k each)
#pragma unroll
    for (int j = 0; j < 32; j++) {
        int lin = j * 256 + tid;        // 0..8191
        int mat = lin >> 11;            // 0..3
        int within = lin & 2047;
        int row = within >> 6;          // 0..31
        int seg = within & 63;
        size_t gcol = (size_t)((row >> 3) * HID_SZ + hu0 + (row & 7));
        const __half* src;
        if (mat == 0)      src = g_WHH + gcol * HID_SZ + seg * 8;
        else if (mat == 1) src = g_WHL + gcol * HID_SZ + seg * 8;
        else if (mat == 2) src = g_WXH + gcol * IN_SZ + seg * 8;
        else               src = g_WXL + gcol * IN_SZ + seg * 8;
        cpasync16(sb + (uint32_t)mat * 33280 + row * 1040 + seg * 16, src);
    }
    cpasync_commit();

    // pointwise slot: (local batch pb, unit pj)
    const int pb = tid >> 3;
    const int pj = tid & 7;
    const int bg = bh * 32 + pb;

    float creg = c0[bg * HID_SZ + hu0 + pj];
    const float bi_r = bias[0 * HID_SZ + hu0 + pj];
    const float bf_r = bias[1 * HID_SZ + hu0 + pj];
    const float bo_r = bias[2 * HID_SZ + hu0 + pj];
    const float bc_r = bias[3 * HID_SZ + hu0 + pj];

    // init H buffer 0 and publish flag=1
    st_cg_h16(&g_HB[0][bg * HID_SZ + hu0 + pj],
              __float2half_rn(h0[bg * HID_SZ + hu0 + pj]));
    asm volatile("cp.async.wait_group 0;");   // W slices resident
    __syncthreads();
    if (tid == 0) { __threadfence(); st_rel(&g_flags[cta * 32], 1u); }
    if (tid < 64) { while (ld_rlx(&g_flags[(tid * 2 + bh) * 32]) < 1u) { } }
    fence_acq();
    __syncthreads();

    // prologue: stage X[0], compute XG(0) partial into accx
    float accx[2][4];
#pragma unroll
    for (int n = 0; n < 2; n++)
#pragma unroll
        for (int c = 0; c < 4; c++) accx[n][c] = 0.0f;

    stage_x(sb, 0, bh, tid);
    asm volatile("cp.async.wait_group 0;");
    __syncthreads();
#pragma unroll
    for (int s = 0; s < 16; s++) {
        uint32_t xh[4], wh[4], wl[4];
        uint32_t ra = sb + XB + (uint32_t)(wm * 16 + a_radd) * 1040 +
                      (wk * 256 + s * 16 + a_kadd) * 2;
        ldsm4(xh, ra);
        uint32_t rb = sb + WXB + (uint32_t)(wn * 16 + b_nadd) * 1040 +
                      (wk * 256 + s * 16 + b_kadd) * 2;
        ldsm4(wh, rb);
        ldsm4(wl, rb + 33280);
#pragma unroll
        for (int hf = 0; hf < 2; hf++) {
            mma16816f(accx[hf], xh, &wh[2 * hf]);
            mma16816f(accx[hf], xh, &wl[2 * hf]);
        }
    }
    __syncthreads();

    for (int t = 0; t < T_STEPS; t++) {
        const int cur = t & 1;
        const bool has_next = (t + 1 < T_STEPS);

        // stage H(t): group (wk,wm), 2 commit halves (128 k each)
#pragma unroll
        for (int half = 0; half < 2; half++) {
#pragma unroll
            for (int j = 0; j < 4; j++) {
                int lin = j * 64 + gl;          // 0..255
                int r16 = lin >> 4;             // 0..15
                int seg = half * 16 + (lin & 15);
                int row = wm * 16 + r16;
                int b = bh * 32 + row;
                const __half* src =
                    g_HB[cur] + (size_t)b * HID_SZ + wk * 256 + seg * 8;
                cpasync16(sb + HB + (uint32_t)wk * 16896 + row * 528 + seg * 16,
                          src);
            }
            cpasync_commit();
        }
        // stage X[t+1] (overlaps with the recurrent mma below)
        if (has_next) stage_x(sb, t + 1, bh, tid);

        // recurrent mma, accumulators start from this step's XG partial
        float acc[2][4];
#pragma unroll
        for (int n = 0; n < 2; n++)
#pragma unroll
            for (int c = 0; c < 4; c++) acc[n][c] = accx[n][c];

        const uint32_t hbs = sb + HB + (uint32_t)wk * 16896;

        if (has_next) asm volatile("cp.async.wait_group 2;");
        else          asm volatile("cp.async.wait_group 1;");
        asm volatile("bar.sync %0, 64;" :: "r"(grp + 1) : "memory");
#pragma unroll
        for (int s = 0; s < 8; s++) {
            uint32_t ah[4], bhq[4], blq[4];
            uint32_t ra = hbs + (uint32_t)(wm * 16 + a_radd) * 528 +
                          (s * 16 + a_kadd) * 2;
            ldsm4(ah, ra);
            uint32_t rb = sb + (uint32_t)(wn * 16 + b_nadd) * 1040 +
                          (wk * 256 + s * 16 + b_kadd) * 2;
            ldsm4(bhq, rb);
            ldsm4(blq, rb + 33280);
#pragma unroll
            for (int hf = 0; hf < 2; hf++) {
                mma16816f(acc[hf], ah, &bhq[2 * hf]);
                mma16816f(acc[hf], ah, &blq[2 * hf]);
            }
        }
        if (has_next) asm volatile("cp.async.wait_group 1;");
        else          asm volatile("cp.async.wait_group 0;");
        asm volatile("bar.sync %0, 64;" :: "r"(grp + 1) : "memory");
#pragma unroll
        for (int s = 8; s < 16; s++) {
            uint32_t ah[4], bhq[4], blq[4];
            uint32_t ra = hbs + (uint32_t)(wm * 16 + a_radd) * 528 +
                          (s * 16 + a_kadd) * 2;
            ldsm4(ah, ra);
            uint32_t rb = sb + (uint32_t)(wn * 16 + b_nadd) * 1040 +
                          (wk * 256 + s * 16 + b_kadd) * 2;
            ldsm4(bhq, rb);
            ldsm4(blq, rb + 33280);
#pragma unroll
            for (int hf = 0; hf < 2; hf++) {
                mma16816f(acc[hf], ah, &bhq[2 * hf]);
                mma16816f(acc[hf], ah, &blq[2 * hf]);
            }
        }

        // write partial G frags to this k-half's buffer
        {
            float* Gd = wk ? Gs1 : Gs0;
            const int g = lane >> 2, t2 = (lane & 3) * 2;
#pragma unroll
            for (int nt = 0; nt < 2; nt++) {
                int row = wm * 16 + g;
                int col = wn * 16 + nt * 8 + t2;
                *(float2*)&Gd[row * 36 + col] = make_float2(acc[nt][0], acc[nt][1]);
                *(float2*)&Gd[(row + 8) * 36 + col] = make_float2(acc[nt][2], acc[nt][3]);
            }
        }
        __syncthreads();    // Gs ready

        // pointwise LSTM cell
        const unsigned int sense = (unsigned)(t + 2);
        float h;
        {
            float gi = Gs0[pb * 36 + 0  + pj] + Gs1[pb * 36 + 0  + pj] + bi_r;
            float gf = Gs0[pb * 36 + 8  + pj] + Gs1[pb * 36 + 8  + pj] + bf_r;
            float go = Gs0[pb * 36 + 16 + pj] + Gs1[pb * 36 + 16 + pj] + bo_r;
            float gc = Gs0[pb * 36 + 24 + pj] + Gs1[pb * 36 + 24 + pj] + bc_r;
            float I = fsig(gi);
            float F = fsig(gf);
            float O = fsig(go);
            float Ct = ftanh(gc);
            creg = F * creg + I * Ct;
            h = O * ftanh(creg);
        }

        if (has_next) {
            // publish H fp16 straight to L2, arrive on own flag
            st_cg_h16(&g_HB[cur ^ 1][bg * HID_SZ + hu0 + pj], __float2half_rn(h));
            __syncthreads();             // all H stores issued
            if (tid == 0) {
                __threadfence();
                st_rel(&g_flags[cta * 32], sense);
            }
            out[(size_t)(t * B_SZ + bg) * HID_SZ + hu0 + pj] = h;

            // XG(t+1) in the wait window (X landed during recurrent mma)
#pragma unroll
            for (int n = 0; n < 2; n++)
#pragma unroll
                for (int c = 0; c < 4; c++) accx[n][c] = 0.0f;
            asm volatile("cp.async.wait_group 0;");
            __syncthreads();             // everyone's X parts arrived
#pragma unroll
            for (int s = 0; s < 16; s++) {
                uint32_t xh[4], wh[4], wl[4];
                uint32_t ra = sb + XB + (uint32_t)(wm * 16 + a_radd) * 1040 +
                              (wk * 256 + s * 16 + a_kadd) * 2;
                ldsm4(xh, ra);
                uint32_t rb = sb + WXB + (uint32_t)(wn * 16 + b_nadd) * 1040 +
                              (wk * 256 + s * 16 + b_kadd) * 2;
                ldsm4(wh, rb);
                ldsm4(wl, rb + 33280);
#pragma unroll
                for (int hf = 0; hf < 2; hf++) {
                    mma16816f(accx[hf], xh, &wh[2 * hf]);
                    mma16816f(accx[hf], xh, &wl[2 * hf]);
                }
            }

            // relaxed-poll own 64-CTA group, then one acquire fence
            if (tid < 64) {
                while (ld_rlx(&g_flags[(tid * 2 + bh) * 32]) < sense) { }
            }
            fence_acq();
            __syncthreads();
        } else {
            out[(size_t)(t * B_SZ + bg) * HID_SZ + hu0 + pj] = h;
        }
    }
}

// ---------------- launcher ---------------------------------------------------
extern "C" void kernel_launch(void* const* d_in, const int* in_sizes, int n_in,
                              void* d_out, int out_size) {
    const float* X    = (const float*)d_in[0];   // (T,B,IN)
    const float* Wx   = (const float*)d_in[1];   // (4,HID,IN)
    const float* Wh   = (const float*)d_in[2];   // (4,HID,HID)
    const float* bias = (const float*)d_in[3];   // (4,HID)
    const float* thr  = (const float*)d_in[4];   // (HID,8)
    const float* h0   = (const float*)d_in[5];   // (B,HID)
    const float* c0   = (const float*)d_in[6];   // (B,HID)
    float* out = (float*)d_out;                  // (T,B,HID)

    mask_weights<<<(4 * HID_SZ * IN_SZ + 255) / 256, 256>>>(Wx, Wh, thr);
    split_x<<<(M_ROWS * IN_SZ / 4 + 255) / 256, 256>>>(X);

    // reset flags BEFORE lstm (replay-safe: lstm leaves flags at 1024; reset
    // restores 0 so each replay is identical; also aligns ncu capture on lstm)
    reset_flags<<<1, 128>>>();

    cudaFuncSetAttribute(lstm_fused,
                         cudaFuncAttributeMaxDynamicSharedMemorySize, L_SMEM);
    lstm_fused<<<N_CTAS, 256, L_SMEM>>>(h0, c0, bias, out);
}

// round 16
// speedup vs baseline: 1.4859x; 1.0928x over previous
#include <cuda_runtime.h>
#include <cuda_fp16.h>
#include <math.h>
#include <stdint.h>

// Problem constants
#define T_STEPS 1024
#define B_SZ    64
#define IN_SZ   512
#define HID_SZ  512
#define NCOL    2048               // 4 gates * HID
#define M_ROWS  (T_STEPS * B_SZ)   // 65536
#define N_CTAS  128

// ---------------- device scratch (static; no runtime allocation) ------------
__device__ __half g_XF[(size_t)M_ROWS * IN_SZ];   // X fp16 (single), 64 MB
__device__ __half g_WXH[NCOL * IN_SZ];            // Wx hi fp16 [col][k]
__device__ __half g_WXL[NCOL * IN_SZ];            // Wx lo fp16 [col][k]
__device__ __half g_WHH[NCOL * HID_SZ];           // Wh hi fp16 [col][k]
__device__ __half g_HB[2][B_SZ * HID_SZ];         // H fp16 [b][k], dbl buf
__device__ unsigned int g_flags[N_CTAS * 32];     // 1 flag / 128B line

// ---------------- helpers -----------------------------------------------------
__device__ __forceinline__ uint32_t smem_u32(const void* p) {
    uint32_t a;
    asm("{ .reg .u64 t; cvta.to.shared.u64 t, %1; cvt.u32.u64 %0, t; }"
        : "=r"(a) : "l"(p));
    return a;
}
__device__ __forceinline__ void cpasync16(uint32_t smem_dst, const void* gsrc) {
    asm volatile("cp.async.cg.shared.global [%0], [%1], 16;"
                 :: "r"(smem_dst), "l"(gsrc));
}
__device__ __forceinline__ void cpasync_commit() {
    asm volatile("cp.async.commit_group;");
}
__device__ __forceinline__ void ldsm4(uint32_t* r, uint32_t addr) {
    asm volatile("ldmatrix.sync.aligned.m8n8.x4.shared.b16 {%0,%1,%2,%3}, [%4];"
                 : "=r"(r[0]), "=r"(r[1]), "=r"(r[2]), "=r"(r[3]) : "r"(addr));
}
__device__ __forceinline__ void mma16816f(float* c, const uint32_t* a,
                                          const uint32_t* b) {
    asm volatile(
        "mma.sync.aligned.m16n8k16.row.col.f32.f16.f16.f32 "
        "{%0,%1,%2,%3}, {%4,%5,%6,%7}, {%8,%9}, {%0,%1,%2,%3};"
        : "+f"(c[0]), "+f"(c[1]), "+f"(c[2]), "+f"(c[3])
        : "r"(a[0]), "r"(a[1]), "r"(a[2]), "r"(a[3]), "r"(b[0]), "r"(b[1]));
}
__device__ __forceinline__ float fsig(float x) {
    return 1.0f / (1.0f + __expf(-x));
}
__device__ __forceinline__ float ftanh(float x) {
    return 1.0f - 2.0f / (__expf(2.0f * x) + 1.0f);
}
__device__ __forceinline__ unsigned int ld_rlx(const unsigned int* p) {
    unsigned int v;
    asm volatile("ld.relaxed.gpu.global.u32 %0, [%1];" : "=r"(v) : "l"(p) : "memory");
    return v;
}
__device__ __forceinline__ void st_rel(unsigned int* p, unsigned int v) {
    asm volatile("st.release.gpu.global.u32 [%0], %1;" :: "l"(p), "r"(v) : "memory");
}
__device__ __forceinline__ void fence_acq() {
    asm volatile("fence.acq_rel.gpu;" ::: "memory");
}
// L1-bypassing fp16 store (publish path: consumers read from L2 via cp.async)
__device__ __forceinline__ void st_cg_h16(__half* p, __half v) {
    unsigned short u = *reinterpret_cast<unsigned short*>(&v);
    asm volatile("st.global.cg.u16 [%0], %1;" :: "l"(p), "h"(u) : "memory");
}
// streaming fp32 store for `out` (avoid L2 pollution of the H-exchange lines)
__device__ __forceinline__ void st_cs_f32(float* p, float v) {
    asm volatile("st.global.cs.f32 [%0], %1;" :: "l"(p), "f"(v) : "memory");
}

// ---------------- kernel 1: threshold-mask + fp16 weight prep -----------------
__global__ void mask_weights(const float* __restrict__ Wx,
                             const float* __restrict__ Wh,
                             const float* __restrict__ thr) {
    int idx = blockIdx.x * blockDim.x + threadIdx.x;   // over 4*512*512
    if (idx >= 4 * HID_SZ * IN_SZ) return;
    int g = idx / (HID_SZ * IN_SZ);
    int rem = idx % (HID_SZ * IN_SZ);
    int n = rem / IN_SZ;
    int i = rem % IN_SZ;
    size_t o = (size_t)(g * HID_SZ + n) * IN_SZ + i;

    float wx = Wx[idx];
    float vx = (fabsf(wx) >= thr[n * 8 + g]) ? wx : 0.0f;
    __half xh = __float2half_rn(vx);
    g_WXH[o] = xh;
    g_WXL[o] = __float2half_rn(vx - __half2float(xh));

    float wh = Wh[idx];
    float vh = (fabsf(wh) >= thr[n * 8 + 4 + g]) ? wh : 0.0f;
    g_WHH[o] = __float2half_rn(vh);
}

// ---------------- kernel 2: convert X to fp16 ---------------------------------
__global__ void split_x(const float* __restrict__ X) {
    size_t i = ((size_t)blockIdx.x * blockDim.x + threadIdx.x) * 4;
    if (i >= (size_t)M_ROWS * IN_SZ) return;
    float4 x = *(const float4*)&X[i];
    __half2* p = (__half2*)&g_XF[i];
    p[0] = __floats2half2_rn(x.x, x.y);
    p[1] = __floats2half2_rn(x.z, x.w);
}

// ---------------- kernel: reset barrier flags (runs BEFORE lstm) --------------
__global__ void reset_flags() {
    if (threadIdx.x < N_CTAS) g_flags[threadIdx.x * 32] = 0u;
}

// ---------------- kernel 3: fused persistent LSTM (fp16 operands) -------------
// 128 CTAs = 64 col-groups x 2 batch-halves; CTA = 32 batches x 32 gate-cols.
// 8 warps = 2k x 2m x 2n. Resident: Whh (single product on the critical
// recurrent path) + Wxh/Wxl (2 products, latency-hidden XG loop). H, X fp16.
// Per step: stage H (1 commit) + X[t+1] (1 commit) -> recurrent mma ->
// Gs reduce -> pointwise + publish + flag -> XG(t+1) in wait window -> poll.
#define WHB   0                     // Whh: 32 rows x 1040B = 33280
#define WXB   33280                 // Wxh, then Wxl at +33280
#define HB    99840                 // H: 2 k-chunks x 16896 (32 rows x 528B)
#define XB    133632                // X: 32 rows x 1040B = 33280
#define GSB   166912                // Gs: 2 x [32][36] f32 = 9216
#define L_SMEM 176128

__device__ __forceinline__ void stage_x(uint32_t sb, int tstep, int bh, int tid) {
#pragma unroll
    for (int j = 0; j < 8; j++) {
        int lin = j * 256 + tid;        // 0..2047
        int row = lin >> 6;             // 0..31
        int seg = lin & 63;             // 16B segment (512 halves)
        const __half* src =
            g_XF + ((size_t)(tstep * B_SZ + bh * 32 + row)) * IN_SZ + seg * 8;
        cpasync16(sb + XB + row * 1040 + seg * 16, src);
    }
    cpasync_commit();
}

__global__ void __launch_bounds__(256, 1)
lstm_fused(const float* __restrict__ h0, const float* __restrict__ c0,
           const float* __restrict__ bias, float* __restrict__ out) {
    extern __shared__ char sm[];
    const uint32_t sb = smem_u32(sm);
    float* Gs0 = (float*)(sm + GSB);                 // [32][36] partial k0
    float* Gs1 = Gs0 + 32 * 36;                      // [32][36] partial k1

    const int tid = threadIdx.x;
    const int wid = tid >> 5;
    const int lane = tid & 31;
    const int wk = wid & 1;         // k-half
    const int wm = (wid >> 1) & 1;  // m-tile (16 batches)
    const int wn = wid >> 2;        // n-tile (16 cols)
    const int grp = wid & 3;        // staging group (wk, wm)
    const int gl = wn * 32 + lane;  // lane within 64-thread group

    const int cta = blockIdx.x;
    const int cg  = cta >> 1;             // col group 0..63
    const int bh  = cta & 1;              // batch half
    const int hu0 = cg * 8;

    const int a_radd = ((lane >> 3) & 1) * 8 + (lane & 7);
    const int a_kadd = ((lane >> 4) & 1) * 8;
    const int b_nadd = ((lane >> 4) & 1) * 8 + (lane & 7);
    const int b_kadd = ((lane >> 3) & 1) * 8;

    // Load resident W: WHH, WXH, WXL (32 rows x 512 k each) = 6144 x 16B
#pragma unroll
    for (int j = 0; j < 24; j++) {
        int lin = j * 256 + tid;        // 0..6143
        int mat = lin >> 11;            // 0..2
        int within = lin & 2047;
        int row = within >> 6;          // 0..31
        int seg = within & 63;
        size_t gcol = (size_t)((row >> 3) * HID_SZ + hu0 + (row & 7));
        const __half* src;
        if (mat == 0)      src = g_WHH + gcol * HID_SZ + seg * 8;
        else if (mat == 1) src = g_WXH + gcol * IN_SZ + seg * 8;
        else               src = g_WXL + gcol * IN_SZ + seg * 8;
        cpasync16(sb + (uint32_t)mat * 33280 + row * 1040 + seg * 16, src);
    }
    cpasync_commit();

    // pointwise slot: (local batch pb, unit pj)
    const int pb = tid >> 3;
    const int pj = tid & 7;
    const int bg = bh * 32 + pb;

    float creg = c0[bg * HID_SZ + hu0 + pj];
    const float bi_r = bias[0 * HID_SZ + hu0 + pj];
    const float bf_r = bias[1 * HID_SZ + hu0 + pj];
    const float bo_r = bias[2 * HID_SZ + hu0 + pj];
    const float bc_r = bias[3 * HID_SZ + hu0 + pj];

    // init H buffer 0 and publish flag=1
    st_cg_h16(&g_HB[0][bg * HID_SZ + hu0 + pj],
              __float2half_rn(h0[bg * HID_SZ + hu0 + pj]));
    asm volatile("cp.async.wait_group 0;");   // W slices resident
    __syncthreads();
    if (tid == 0) { __threadfence(); st_rel(&g_flags[cta * 32], 1u); }
    if (tid < 64) { while (ld_rlx(&g_flags[(tid * 2 + bh) * 32]) < 1u) { } }
    fence_acq();
    __syncthreads();

    // prologue: stage X[0], compute XG(0) partial into accx
    float accx[2][4];
#pragma unroll
    for (int n = 0; n < 2; n++)
#pragma unroll
        for (int c = 0; c < 4; c++) accx[n][c] = 0.0f;

    stage_x(sb, 0, bh, tid);
    asm volatile("cp.async.wait_group 0;");
    __syncthreads();
#pragma unroll
    for (int s = 0; s < 16; s++) {
        uint32_t xh[4], wh[4], wl[4];
        uint32_t ra = sb + XB + (uint32_t)(wm * 16 + a_radd) * 1040 +
                      (wk * 256 + s * 16 + a_kadd) * 2;
        ldsm4(xh, ra);
        uint32_t rb = sb + WXB + (uint32_t)(wn * 16 + b_nadd) * 1040 +
                      (wk * 256 + s * 16 + b_kadd) * 2;
        ldsm4(wh, rb);
        ldsm4(wl, rb + 33280);
#pragma unroll
        for (int hf = 0; hf < 2; hf++) {
            mma16816f(accx[hf], xh, &wh[2 * hf]);
            mma16816f(accx[hf], xh, &wl[2 * hf]);
        }
    }
    __syncthreads();

    for (int t = 0; t < T_STEPS; t++) {
        const int cur = t & 1;
        const bool has_next = (t + 1 < T_STEPS);

        // stage H(t): group (wk,wm), ONE commit (rows wm*16..+16, k-half wk)
#pragma unroll
        for (int j = 0; j < 8; j++) {
            int lin = j * 64 + gl;          // 0..511
            int r16 = lin >> 5;             // 0..15
            int seg = lin & 31;             // 16B seg of 512B row
            int row = wm * 16 + r16;
            int b = bh * 32 + row;
            const __half* src =
                g_HB[cur] + (size_t)b * HID_SZ + wk * 256 + seg * 8;
            cpasync16(sb + HB + (uint32_t)wk * 16896 + row * 528 + seg * 16,
                      src);
        }
        cpasync_commit();
        // stage X[t+1] (overlaps with the recurrent mma below)
        if (has_next) stage_x(sb, t + 1, bh, tid);

        // recurrent mma (single product), acc init = this step's XG partial
        float acc[2][4];
#pragma unroll
        for (int n = 0; n < 2; n++)
#pragma unroll
            for (int c = 0; c < 4; c++) acc[n][c] = accx[n][c];

        const uint32_t hbs = sb + HB + (uint32_t)wk * 16896;

        if (has_next) asm volatile("cp.async.wait_group 1;");
        else          asm volatile("cp.async.wait_group 0;");
        asm volatile("bar.sync %0, 64;" :: "r"(grp + 1) : "memory");
#pragma unroll
        for (int s = 0; s < 16; s++) {
            uint32_t ah[4], bhq[4];
            uint32_t ra = hbs + (uint32_t)(wm * 16 + a_radd) * 528 +
                          (s * 16 + a_kadd) * 2;
            ldsm4(ah, ra);
            uint32_t rb = sb + WHB + (uint32_t)(wn * 16 + b_nadd) * 1040 +
                          (wk * 256 + s * 16 + b_kadd) * 2;
            ldsm4(bhq, rb);
#pragma unroll
            for (int hf = 0; hf < 2; hf++)
                mma16816f(acc[hf], ah, &bhq[2 * hf]);
        }

        // write partial G frags to this k-half's buffer
        {
            float* Gd = wk ? Gs1 : Gs0;
            const int g = lane >> 2, t2 = (lane & 3) * 2;
#pragma unroll
            for (int nt = 0; nt < 2; nt++) {
                int row = wm * 16 + g;
                int col = wn * 16 + nt * 8 + t2;
                *(float2*)&Gd[row * 36 + col] = make_float2(acc[nt][0], acc[nt][1]);
                *(float2*)&Gd[(row + 8) * 36 + col] = make_float2(acc[nt][2], acc[nt][3]);
            }
        }
        __syncthreads();    // Gs ready

        // pointwise LSTM cell
        const unsigned int sense = (unsigned)(t + 2);
        float h;
        {
            float gi = Gs0[pb * 36 + 0  + pj] + Gs1[pb * 36 + 0  + pj] + bi_r;
            float gf = Gs0[pb * 36 + 8  + pj] + Gs1[pb * 36 + 8  + pj] + bf_r;
            float go = Gs0[pb * 36 + 16 + pj] + Gs1[pb * 36 + 16 + pj] + bo_r;
            float gc = Gs0[pb * 36 + 24 + pj] + Gs1[pb * 36 + 24 + pj] + bc_r;
            float I = fsig(gi);
            float F = fsig(gf);
            float O = fsig(go);
            float Ct = ftanh(gc);
            creg = F * creg + I * Ct;
            h = O * ftanh(creg);
        }

        if (has_next) {
            // publish H fp16 straight to L2, arrive on own flag
            st_cg_h16(&g_HB[cur ^ 1][bg * HID_SZ + hu0 + pj], __float2half_rn(h));
            __syncthreads();             // all H stores issued
            if (tid == 0) {
                __threadfence();
                st_rel(&g_flags[cta * 32], sense);
            }
            st_cs_f32(&out[(size_t)(t * B_SZ + bg) * HID_SZ + hu0 + pj], h);

            // XG(t+1) in the wait window (X landed during recurrent mma)
#pragma unroll
            for (int n = 0; n < 2; n++)
#pragma unroll
                for (int c = 0; c < 4; c++) accx[n][c] = 0.0f;
            asm volatile("cp.async.wait_group 0;");
            __syncthreads();             // everyone's X parts arrived
#pragma unroll
            for (int s = 0; s < 16; s++) {
                uint32_t xh[4], wh[4], wl[4];
                uint32_t ra = sb + XB + (uint32_t)(wm * 16 + a_radd) * 1040 +
                              (wk * 256 + s * 16 + a_kadd) * 2;
                ldsm4(xh, ra);
                uint32_t rb = sb + WXB + (uint32_t)(wn * 16 + b_nadd) * 1040 +
                              (wk * 256 + s * 16 + b_kadd) * 2;
                ldsm4(wh, rb);
                ldsm4(wl, rb + 33280);
#pragma unroll
                for (int hf = 0; hf < 2; hf++) {
                    mma16816f(accx[hf], xh, &wh[2 * hf]);
                    mma16816f(accx[hf], xh, &wl[2 * hf]);
                }
            }

            // relaxed-poll own 64-CTA group, then one acquire fence
            if (tid < 64) {
                while (ld_rlx(&g_flags[(tid * 2 + bh) * 32]) < sense) { }
            }
            fence_acq();
            __syncthreads();
        } else {
            st_cs_f32(&out[(size_t)(t * B_SZ + bg) * HID_SZ + hu0 + pj], h);
        }
    }
}

// ---------------- launcher ---------------------------------------------------
extern "C" void kernel_launch(void* const* d_in, const int* in_sizes, int n_in,
                              void* d_out, int out_size) {
    const float* X    = (const float*)d_in[0];   // (T,B,IN)
    const float* Wx   = (const float*)d_in[1];   // (4,HID,IN)
    const float* Wh   = (const float*)d_in[2];   // (4,HID,HID)
    const float* bias = (const float*)d_in[3];   // (4,HID)
    const float* thr  = (const float*)d_in[4];   // (HID,8)
    const float* h0   = (const float*)d_in[5];   // (B,HID)
    const float* c0   = (const float*)d_in[6];   // (B,HID)
    float* out = (float*)d_out;                  // (T,B,HID)

    mask_weights<<<(4 * HID_SZ * IN_SZ + 255) / 256, 256>>>(Wx, Wh, thr);
    split_x<<<(M_ROWS * IN_SZ / 4 + 255) / 256, 256>>>(X);

    // reset flags BEFORE lstm (replay-safe; aligns ncu capture on lstm)
    reset_flags<<<1, 128>>>();

    cudaFuncSetAttribute(lstm_fused,
                         cudaFuncAttributeMaxDynamicSharedMemorySize, L_SMEM);
    lstm_fused<<<N_CTAS, 256, L_SMEM>>>(h0, c0, bias, out);
}

// round 17
// speedup vs baseline: 1.7262x; 1.1617x over previous
#include <cuda_runtime.h>
#include <cuda_fp16.h>
#include <math.h>
#include <stdint.h>

// Problem constants
#define T_STEPS 1024
#define B_SZ    64
#define IN_SZ   512
#define HID_SZ  512
#define NCOL    2048               // 4 gates * HID
#define M_ROWS  (T_STEPS * B_SZ)   // 65536
#define N_CTAS  128

// ---------------- device scratch (static; no runtime allocation) ------------
__device__ __half g_XF[(size_t)M_ROWS * IN_SZ];   // X fp16, 64 MB
__device__ __half g_WXH[NCOL * IN_SZ];            // Wx fp16 [col][k]
__device__ __half g_WHH[NCOL * HID_SZ];           // Wh fp16 [col][k]
__device__ __half g_HB[2][B_SZ * HID_SZ];         // H fp16 [b][k], dbl buf
__device__ unsigned int g_flags[N_CTAS * 32];     // 1 flag / 128B line

// ---------------- helpers -----------------------------------------------------
__device__ __forceinline__ uint32_t smem_u32(const void* p) {
    uint32_t a;
    asm("{ .reg .u64 t; cvta.to.shared.u64 t, %1; cvt.u32.u64 %0, t; }"
        : "=r"(a) : "l"(p));
    return a;
}
__device__ __forceinline__ void cpasync16(uint32_t smem_dst, const void* gsrc) {
    asm volatile("cp.async.cg.shared.global [%0], [%1], 16;"
                 :: "r"(smem_dst), "l"(gsrc));
}
__device__ __forceinline__ void cpasync_commit() {
    asm volatile("cp.async.commit_group;");
}
__device__ __forceinline__ void ldsm4(uint32_t* r, uint32_t addr) {
    asm volatile("ldmatrix.sync.aligned.m8n8.x4.shared.b16 {%0,%1,%2,%3}, [%4];"
                 : "=r"(r[0]), "=r"(r[1]), "=r"(r[2]), "=r"(r[3]) : "r"(addr));
}
__device__ __forceinline__ void mma16816f(float* c, const uint32_t* a,
                                          const uint32_t* b) {
    asm volatile(
        "mma.sync.aligned.m16n8k16.row.col.f32.f16.f16.f32 "
        "{%0,%1,%2,%3}, {%4,%5,%6,%7}, {%8,%9}, {%0,%1,%2,%3};"
        : "+f"(c[0]), "+f"(c[1]), "+f"(c[2]), "+f"(c[3])
        : "r"(a[0]), "r"(a[1]), "r"(a[2]), "r"(a[3]), "r"(b[0]), "r"(b[1]));
}
__device__ __forceinline__ float fsig(float x) {
    return 1.0f / (1.0f + __expf(-x));
}
__device__ __forceinline__ float ftanh(float x) {
    return 1.0f - 2.0f / (__expf(2.0f * x) + 1.0f);
}
__device__ __forceinline__ unsigned int ld_rlx(const unsigned int* p) {
    unsigned int v;
    asm volatile("ld.relaxed.gpu.global.u32 %0, [%1];" : "=r"(v) : "l"(p) : "memory");
    return v;
}
__device__ __forceinline__ void st_rel(unsigned int* p, unsigned int v) {
    asm volatile("st.release.gpu.global.u32 [%0], %1;" :: "l"(p), "r"(v) : "memory");
}
__device__ __forceinline__ void fence_acq() {
    asm volatile("fence.acq_rel.gpu;" ::: "memory");
}
// L1-bypassing fp16 store (publish path: consumers read from L2 via cp.async)
__device__ __forceinline__ void st_cg_h16(__half* p, __half v) {
    unsigned short u = *reinterpret_cast<unsigned short*>(&v);
    asm volatile("st.global.cg.u16 [%0], %1;" :: "l"(p), "h"(u) : "memory");
}
// streaming fp32 store for `out` (avoid L2 pollution of the H-exchange lines)
__device__ __forceinline__ void st_cs_f32(float* p, float v) {
    asm volatile("st.global.cs.f32 [%0], %1;" :: "l"(p), "f"(v) : "memory");
}

// ---------------- kernel 1: threshold-mask + fp16 weight prep -----------------
__global__ void mask_weights(const float* __restrict__ Wx,
                             const float* __restrict__ Wh,
                             const float* __restrict__ thr) {
    int idx = blockIdx.x * blockDim.x + threadIdx.x;   // over 4*512*512
    if (idx >= 4 * HID_SZ * IN_SZ) return;
    int g = idx / (HID_SZ * IN_SZ);
    int rem = idx % (HID_SZ * IN_SZ);
    int n = rem / IN_SZ;
    int i = rem % IN_SZ;
    size_t o = (size_t)(g * HID_SZ + n) * IN_SZ + i;

    float wx = Wx[idx];
    float vx = (fabsf(wx) >= thr[n * 8 + g]) ? wx : 0.0f;
    g_WXH[o] = __float2half_rn(vx);

    float wh = Wh[idx];
    float vh = (fabsf(wh) >= thr[n * 8 + 4 + g]) ? wh : 0.0f;
    g_WHH[o] = __float2half_rn(vh);
}

// ---------------- kernel 2: convert X to fp16 ---------------------------------
__global__ void split_x(const float* __restrict__ X) {
    size_t i = ((size_t)blockIdx.x * blockDim.x + threadIdx.x) * 4;
    if (i >= (size_t)M_ROWS * IN_SZ) return;
    float4 x = *(const float4*)&X[i];
    __half2* p = (__half2*)&g_XF[i];
    p[0] = __floats2half2_rn(x.x, x.y);
    p[1] = __floats2half2_rn(x.z, x.w);
}

// ---------------- kernel: reset barrier flags (runs BEFORE lstm) --------------
__global__ void reset_flags() {
    if (threadIdx.x < N_CTAS) g_flags[threadIdx.x * 32] = 0u;
}

// ---------------- kernel 3: fused persistent LSTM (fp16 operands) -------------
// 128 CTAs = 64 col-groups x 2 batch-halves; CTA = 32 batches x 32 gate-cols.
// 8 warps = 2k x 2m x 2n. Wh FRAGMENTS REGISTER-RESIDENT (loaded once);
// Wxh SMEM-resident. H, X single fp16. Per step: stage H (1 commit) + X[t+1]
// (1 commit) -> recurrent mma (1 ldsm + 2 mma per s) -> Gs reduce ->
// pointwise + publish + release-flag -> XG(t+1) (2 ldsm + 2 mma per s) -> poll.
#define WHB   0                     // Whh: 32 rows x 1040B = 33280
#define WXB   33280                 // Wxh: 33280
#define HB    66560                 // H: 2 k-chunks x 16896 (32 rows x 528B)
#define XB    100352                // X: 32 rows x 1040B = 33280
#define GSB   133632                // Gs: 2 x [32][36] f32 = 9216
#define L_SMEM 142848

__device__ __forceinline__ void stage_x(uint32_t sb, int tstep, int bh, int tid) {
#pragma unroll
    for (int j = 0; j < 8; j++) {
        int lin = j * 256 + tid;        // 0..2047
        int row = lin >> 6;             // 0..31
        int seg = lin & 63;             // 16B segment (512 halves)
        const __half* src =
            g_XF + ((size_t)(tstep * B_SZ + bh * 32 + row)) * IN_SZ + seg * 8;
        cpasync16(sb + XB + row * 1040 + seg * 16, src);
    }
    cpasync_commit();
}

__global__ void __launch_bounds__(256, 1)
lstm_fused(const float* __restrict__ h0, const float* __restrict__ c0,
           const float* __restrict__ bias, float* __restrict__ out) {
    extern __shared__ char sm[];
    const uint32_t sb = smem_u32(sm);
    float* Gs0 = (float*)(sm + GSB);                 // [32][36] partial k0
    float* Gs1 = Gs0 + 32 * 36;                      // [32][36] partial k1

    const int tid = threadIdx.x;
    const int wid = tid >> 5;
    const int lane = tid & 31;
    const int wk = wid & 1;         // k-half
    const int wm = (wid >> 1) & 1;  // m-tile (16 batches)
    const int wn = wid >> 2;        // n-tile (16 cols)
    const int grp = wid & 3;        // staging group (wk, wm)
    const int gl = wn * 32 + lane;  // lane within 64-thread group

    const int cta = blockIdx.x;
    const int cg  = cta >> 1;             // col group 0..63
    const int bh  = cta & 1;              // batch half
    const int hu0 = cg * 8;

    const int a_radd = ((lane >> 3) & 1) * 8 + (lane & 7);
    const int a_kadd = ((lane >> 4) & 1) * 8;
    const int b_nadd = ((lane >> 4) & 1) * 8 + (lane & 7);
    const int b_kadd = ((lane >> 3) & 1) * 8;

    // Load resident W: WHH, WXH (32 rows x 512 k each) = 4096 x 16B copies
#pragma unroll
    for (int j = 0; j < 16; j++) {
        int lin = j * 256 + tid;        // 0..4095
        int mat = lin >> 11;            // 0: Whh, 1: Wxh
        int within = lin & 2047;
        int row = within >> 6;          // 0..31
        int seg = within & 63;
        size_t gcol = (size_t)((row >> 3) * HID_SZ + hu0 + (row & 7));
        const __half* src;
        if (mat == 0) src = g_WHH + gcol * HID_SZ + seg * 8;
        else          src = g_WXH + gcol * IN_SZ + seg * 8;
        cpasync16(sb + (uint32_t)mat * 33280 + row * 1040 + seg * 16, src);
    }
    cpasync_commit();

    // pointwise slot: (local batch pb, unit pj)
    const int pb = tid >> 3;
    const int pj = tid & 7;
    const int bg = bh * 32 + pb;

    float creg = c0[bg * HID_SZ + hu0 + pj];
    const float bi_r = bias[0 * HID_SZ + hu0 + pj];
    const float bf_r = bias[1 * HID_SZ + hu0 + pj];
    const float bo_r = bias[2 * HID_SZ + hu0 + pj];
    const float bc_r = bias[3 * HID_SZ + hu0 + pj];

    // init H buffer 0 and publish flag=1
    st_cg_h16(&g_HB[0][bg * HID_SZ + hu0 + pj],
              __float2half_rn(h0[bg * HID_SZ + hu0 + pj]));
    asm volatile("cp.async.wait_group 0;");   // W slices resident
    __syncthreads();
    if (tid == 0) st_rel(&g_flags[cta * 32], 1u);   // release orders prior st
    if (tid < 64) { while (ld_rlx(&g_flags[(tid * 2 + bh) * 32]) < 1u) { } }
    fence_acq();
    __syncthreads();

    // hoist Wh fragments into registers (reused for all 1024 steps)
    uint32_t whf[16][4];
#pragma unroll
    for (int s = 0; s < 16; s++) {
        uint32_t rb = sb + WHB + (uint32_t)(wn * 16 + b_nadd) * 1040 +
                      (wk * 256 + s * 16 + b_kadd) * 2;
        ldsm4(whf[s], rb);
    }

    // prologue: stage X[0], compute XG(0) partial into accx
    float accx[2][4];
#pragma unroll
    for (int n = 0; n < 2; n++)
#pragma unroll
        for (int c = 0; c < 4; c++) accx[n][c] = 0.0f;

    stage_x(sb, 0, bh, tid);
    asm volatile("cp.async.wait_group 0;");
    __syncthreads();
#pragma unroll
    for (int s = 0; s < 16; s++) {
        uint32_t xh[4], wxq[4];
        uint32_t ra = sb + XB + (uint32_t)(wm * 16 + a_radd) * 1040 +
                      (wk * 256 + s * 16 + a_kadd) * 2;
        ldsm4(xh, ra);
        uint32_t rb = sb + WXB + (uint32_t)(wn * 16 + b_nadd) * 1040 +
                      (wk * 256 + s * 16 + b_kadd) * 2;
        ldsm4(wxq, rb);
#pragma unroll
        for (int hf = 0; hf < 2; hf++)
            mma16816f(accx[hf], xh, &wxq[2 * hf]);
    }
    __syncthreads();

    for (int t = 0; t < T_STEPS; t++) {
        const int cur = t & 1;
        const bool has_next = (t + 1 < T_STEPS);

        // stage H(t): group (wk,wm), ONE commit (rows wm*16..+16, k-half wk)
#pragma unroll
        for (int j = 0; j < 8; j++) {
            int lin = j * 64 + gl;          // 0..511
            int r16 = lin >> 5;             // 0..15
            int seg = lin & 31;             // 16B seg of 512B row
            int row = wm * 16 + r16;
            int b = bh * 32 + row;
            const __half* src =
                g_HB[cur] + (size_t)b * HID_SZ + wk * 256 + seg * 8;
            cpasync16(sb + HB + (uint32_t)wk * 16896 + row * 528 + seg * 16,
                      src);
        }
        cpasync_commit();
        // stage X[t+1] (overlaps with the recurrent mma below)
        if (has_next) stage_x(sb, t + 1, bh, tid);

        // recurrent mma (register-resident Wh), acc init = this step's XG
        float acc[2][4];
#pragma unroll
        for (int n = 0; n < 2; n++)
#pragma unroll
            for (int c = 0; c < 4; c++) acc[n][c] = accx[n][c];

        const uint32_t hbs = sb + HB + (uint32_t)wk * 16896;

        if (has_next) asm volatile("cp.async.wait_group 1;");
        else          asm volatile("cp.async.wait_group 0;");
        asm volatile("bar.sync %0, 64;" :: "r"(grp + 1) : "memory");
#pragma unroll
        for (int s = 0; s < 16; s++) {
            uint32_t ah[4];
            uint32_t ra = hbs + (uint32_t)(wm * 16 + a_radd) * 528 +
                          (s * 16 + a_kadd) * 2;
            ldsm4(ah, ra);
#pragma unroll
            for (int hf = 0; hf < 2; hf++)
                mma16816f(acc[hf], ah, &whf[s][2 * hf]);
        }

        // write partial G frags to this k-half's buffer
        {
            float* Gd = wk ? Gs1 : Gs0;
            const int g = lane >> 2, t2 = (lane & 3) * 2;
#pragma unroll
            for (int nt = 0; nt < 2; nt++) {
                int row = wm * 16 + g;
                int col = wn * 16 + nt * 8 + t2;
                *(float2*)&Gd[row * 36 + col] = make_float2(acc[nt][0], acc[nt][1]);
                *(float2*)&Gd[(row + 8) * 36 + col] = make_float2(acc[nt][2], acc[nt][3]);
            }
        }
        __syncthreads();    // Gs ready

        // pointwise LSTM cell
        const unsigned int sense = (unsigned)(t + 2);
        float h;
        {
            float gi = Gs0[pb * 36 + 0  + pj] + Gs1[pb * 36 + 0  + pj] + bi_r;
            float gf = Gs0[pb * 36 + 8  + pj] + Gs1[pb * 36 + 8  + pj] + bf_r;
            float go = Gs0[pb * 36 + 16 + pj] + Gs1[pb * 36 + 16 + pj] + bo_r;
            float gc = Gs0[pb * 36 + 24 + pj] + Gs1[pb * 36 + 24 + pj] + bc_r;
            float I = fsig(gi);
            float F = fsig(gf);
            float O = fsig(go);
            float Ct = ftanh(gc);
            creg = F * creg + I * Ct;
            h = O * ftanh(creg);
        }

        if (has_next) {
            // publish H fp16 straight to L2, release-arrive on own flag
            st_cg_h16(&g_HB[cur ^ 1][bg * HID_SZ + hu0 + pj], __float2half_rn(h));
            __syncthreads();             // all H stores issued
            if (tid == 0) st_rel(&g_flags[cta * 32], sense);
            st_cs_f32(&out[(size_t)(t * B_SZ + bg) * HID_SZ + hu0 + pj], h);

            // XG(t+1) (X landed during recurrent mma)
#pragma unroll
            for (int n = 0; n < 2; n++)
#pragma unroll
                for (int c = 0; c < 4; c++) accx[n][c] = 0.0f;
            asm volatile("cp.async.wait_group 0;");
            __syncthreads();             // everyone's X parts arrived
#pragma unroll
            for (int s = 0; s < 16; s++) {
                uint32_t xh[4], wxq[4];
                uint32_t ra = sb + XB + (uint32_t)(wm * 16 + a_radd) * 1040 +
                              (wk * 256 + s * 16 + a_kadd) * 2;
                ldsm4(xh, ra);
                uint32_t rb = sb + WXB + (uint32_t)(wn * 16 + b_nadd) * 1040 +
                              (wk * 256 + s * 16 + b_kadd) * 2;
                ldsm4(wxq, rb);
#pragma unroll
                for (int hf = 0; hf < 2; hf++)
                    mma16816f(accx[hf], xh, &wxq[2 * hf]);
            }

            // relaxed-poll own 64-CTA group, then one acquire fence
            if (tid < 64) {
                while (ld_rlx(&g_flags[(tid * 2 + bh) * 32]) < sense) { }
            }
            fence_acq();
            __syncthreads();
        } else {
            st_cs_f32(&out[(size_t)(t * B_SZ + bg) * HID_SZ + hu0 + pj], h);
        }
    }
}

// ---------------- launcher ---------------------------------------------------
extern "C" void kernel_launch(void* const* d_in, const int* in_sizes, int n_in,
                              void* d_out, int out_size) {
    const float* X    = (const float*)d_in[0];   // (T,B,IN)
    const float* Wx   = (const float*)d_in[1];   // (4,HID,IN)
    const float* Wh   = (const float*)d_in[2];   // (4,HID,HID)
    const float* bias = (const float*)d_in[3];   // (4,HID)
    const float* thr  = (const float*)d_in[4];   // (HID,8)
    const float* h0   = (const float*)d_in[5];   // (B,HID)
    const float* c0   = (const float*)d_in[6];   // (B,HID)
    float* out = (float*)d_out;                  // (T,B,HID)

    mask_weights<<<(4 * HID_SZ * IN_SZ + 255) / 256, 256>>>(Wx, Wh, thr);
    split_x<<<(M_ROWS * IN_SZ / 4 + 255) / 256, 256>>>(X);

    // reset flags BEFORE lstm (replay-safe; aligns ncu capture on lstm)
    reset_flags<<<1, 128>>>();

    cudaFuncSetAttribute(lstm_fused,
                         cudaFuncAttributeMaxDynamicSharedMemorySize, L_SMEM);
    lstm_fused<<<N_CTAS, 256, L_SMEM>>>(h0, c0, bias, out);
}